// round 2
// baseline (speedup 1.0000x reference)
#include <cuda_runtime.h>
#include <stdint.h>

// ---------------------------------------------------------------------------
// MagnitudePruning via 2-level radix select on s = t*magnitude + |x|
// (monotone surrogate: division by uniform (t+1) preserves rank).
//
// Pass 1: 12-bit top histogram (shared, warp-aggregated)       360 MB read
// select1: bin b1 + remaining rank r1
// Pass 2 (fused): write out for all non-b1 elements, compact   540 MB r/w
//         b1-candidates {key,idx} + low-20-bit candidate hist
// partial2/select2: exact threshold key among candidates
// finalize: rewrite kept candidates only                        tiny
// ---------------------------------------------------------------------------

#define HIST1_SIZE 4096u          // top 12 bits
#define HIST2_SIZE (1u << 20)     // low 20 bits
#define NBLOCKS 1184              // 8 * 148 SMs
#define NTHREADS 256
#define N_MAX 45088768u

__device__ unsigned int g_hist1[HIST1_SIZE];
__device__ unsigned int g_hist2[HIST2_SIZE];
__device__ unsigned int g_partial[1024];
__device__ unsigned int g_b1;
__device__ unsigned int g_r1;       // 1-based remaining rank within bin b1
__device__ unsigned int g_thr_key;
__device__ unsigned int g_ncand;
__device__ uint2        g_cand[N_MAX];   // {key, idx} for elements in bin b1

__device__ __forceinline__ unsigned int key_of(float x, float m, float tf) {
    // s = t*m + |x|, explicit non-fused rounding so all passes agree bit-exactly
    float s = __fadd_rn(__fmul_rn(tf, m), fabsf(x));
    return __float_as_uint(s);   // s >= 0 -> bits are order-preserving
}

__device__ __forceinline__ float read_tf(const int* t_ptr) {
    return t_ptr ? (float)(*t_ptr) : 1.0f;
}

// ---------------------------------------------------------------------------
__global__ void zero_kernel() {
    unsigned total = HIST2_SIZE + HIST1_SIZE;
    unsigned stride = gridDim.x * blockDim.x;
    for (unsigned i = blockIdx.x * blockDim.x + threadIdx.x; i < total; i += stride) {
        if (i < HIST2_SIZE) g_hist2[i] = 0u;
        else                g_hist1[i - HIST2_SIZE] = 0u;
    }
    if (blockIdx.x == 0 && threadIdx.x == 0) g_ncand = 0u;
}

// ---------------------------------------------------------------------------
__device__ __forceinline__ void agg_shared_add(unsigned* hist, unsigned bin) {
    unsigned act   = __activemask();
    unsigned peers = __match_any_sync(act, bin);
    int      leader = __ffs(peers) - 1;
    if ((int)(threadIdx.x & 31) == leader)
        atomicAdd(&hist[bin], (unsigned)__popc(peers));
}

__global__ void hist1_kernel(const float* __restrict__ xs,
                             const float* __restrict__ ms,
                             const int* __restrict__ t_ptr,
                             unsigned n) {
    __shared__ unsigned sh[HIST1_SIZE];
    for (unsigned i = threadIdx.x; i < HIST1_SIZE; i += blockDim.x) sh[i] = 0u;
    __syncthreads();

    float tf = read_tf(t_ptr);
    unsigned n4 = n >> 2;
    const float4* x4 = (const float4*)xs;
    const float4* m4 = (const float4*)ms;
    unsigned stride = gridDim.x * blockDim.x;
    for (unsigned i = blockIdx.x * blockDim.x + threadIdx.x; i < n4; i += stride) {
        float4 xv = x4[i];
        float4 mv = m4[i];
        agg_shared_add(sh, key_of(xv.x, mv.x, tf) >> 20);
        agg_shared_add(sh, key_of(xv.y, mv.y, tf) >> 20);
        agg_shared_add(sh, key_of(xv.z, mv.z, tf) >> 20);
        agg_shared_add(sh, key_of(xv.w, mv.w, tf) >> 20);
    }
    // scalar tail
    if (blockIdx.x == 0 && threadIdx.x == 0) {
        for (unsigned i = n4 << 2; i < n; i++)
            atomicAdd(&g_hist1[key_of(xs[i], ms[i], tf) >> 20], 1u);
    }
    __syncthreads();
    for (unsigned i = threadIdx.x; i < HIST1_SIZE; i += blockDim.x) {
        unsigned c = sh[i];
        if (c) atomicAdd(&g_hist1[i], c);
    }
}

// ---------------------------------------------------------------------------
// 1 block, 1024 threads. Computes rank R from sparsity and scans the 4096-bin
// histogram to find bin b1 and the remaining rank r1 (1-based).
__global__ void select1_kernel(const float* __restrict__ sparsity, unsigned n) {
    __shared__ unsigned s[1024];
    int t = threadIdx.x;

    unsigned c0 = g_hist1[t * 4 + 0];
    unsigned c1 = g_hist1[t * 4 + 1];
    unsigned c2 = g_hist1[t * 4 + 2];
    unsigned c3 = g_hist1[t * 4 + 3];
    unsigned local = c0 + c1 + c2 + c3;

    s[t] = local;
    __syncthreads();
    for (int off = 1; off < 1024; off <<= 1) {
        unsigned v = (t >= off) ? s[t - off] : 0u;
        __syncthreads();
        s[t] += v;
        __syncthreads();
    }

    // R = idx+1, idx = clip((int)floor(sparsity*n - 1), 0, n-1)  (fp32 math, like jnp)
    float sp   = sparsity[0];
    float fidx = floorf(__fsub_rn(__fmul_rn(sp, (float)n), 1.0f));
    long long idx = (long long)fidx;
    if (idx < 0) idx = 0;
    if (idx > (long long)(n - 1)) idx = (long long)(n - 1);
    unsigned R = (unsigned)idx + 1u;

    unsigned incl   = s[t];
    unsigned before = incl - local;
    if (R > before && R <= incl) {
        unsigned run = before;
        unsigned c[4] = {c0, c1, c2, c3};
        #pragma unroll
        for (int j = 0; j < 4; j++) {
            if (R <= run + c[j]) {
                g_b1 = (unsigned)(t * 4 + j);
                g_r1 = R - run;
                break;
            }
            run += c[j];
        }
    }
}

// ---------------------------------------------------------------------------
// Fused pass: decide all elements whose top-12 bits != b1, compact the rest.
// Candidates get a provisional 0 in out; finalize_kernel writes kept ones.
__device__ __forceinline__ float decide_or_compact(float x, unsigned key,
                                                   unsigned b1, unsigned idx) {
    unsigned top = key >> 20;
    bool cand = (top == b1);
    float ov = (top > b1) ? x : 0.0f;   // cand lanes: top==b1 -> 0 provisional

    unsigned act  = __activemask();
    unsigned ball = __ballot_sync(act, cand);
    if (ball) {
        int leader = __ffs(ball) - 1;
        unsigned base = 0;
        if ((int)(threadIdx.x & 31) == leader)
            base = atomicAdd(&g_ncand, (unsigned)__popc(ball));
        base = __shfl_sync(act, base, leader);
        if (cand) {
            unsigned pos = base + (unsigned)__popc(ball & ((1u << (threadIdx.x & 31)) - 1u));
            g_cand[pos] = make_uint2(key, idx);
            atomicAdd(&g_hist2[key & 0xFFFFFu], 1u);
        }
    }
    return ov;
}

__global__ void apply_compact_kernel(const float* __restrict__ xs,
                                     const float* __restrict__ ms,
                                     const int* __restrict__ t_ptr,
                                     float* __restrict__ out,
                                     unsigned n) {
    float tf = read_tf(t_ptr);
    unsigned b1 = g_b1;
    unsigned n4 = n >> 2;
    const float4* x4 = (const float4*)xs;
    const float4* m4 = (const float4*)ms;
    float4* o4 = (float4*)out;
    unsigned stride = gridDim.x * blockDim.x;
    for (unsigned i = blockIdx.x * blockDim.x + threadIdx.x; i < n4; i += stride) {
        float4 xv = x4[i];
        float4 mv = m4[i];
        unsigned base = i * 4u;
        float4 ov;
        ov.x = decide_or_compact(xv.x, key_of(xv.x, mv.x, tf), b1, base + 0u);
        ov.y = decide_or_compact(xv.y, key_of(xv.y, mv.y, tf), b1, base + 1u);
        ov.z = decide_or_compact(xv.z, key_of(xv.z, mv.z, tf), b1, base + 2u);
        ov.w = decide_or_compact(xv.w, key_of(xv.w, mv.w, tf), b1, base + 3u);
        o4[i] = ov;
    }
    if (blockIdx.x == 0 && threadIdx.x == 0) {
        for (unsigned i = n4 << 2; i < n; i++) {
            unsigned k = key_of(xs[i], ms[i], tf);
            unsigned top = k >> 20;
            out[i] = (top > b1) ? xs[i] : 0.0f;
            if (top == b1) {
                unsigned pos = atomicAdd(&g_ncand, 1u);
                g_cand[pos] = make_uint2(k, i);
                atomicAdd(&g_hist2[k & 0xFFFFFu], 1u);
            }
        }
    }
}

// ---------------------------------------------------------------------------
// 1024 blocks x 256 threads: chunk sums of the 1M-bin candidate histogram.
__global__ void partial2_kernel() {
    __shared__ unsigned red[256];
    unsigned base = blockIdx.x * 1024u;
    unsigned sum = 0;
    for (unsigned i = threadIdx.x; i < 1024u; i += 256u) sum += g_hist2[base + i];
    red[threadIdx.x] = sum;
    __syncthreads();
    for (int off = 128; off > 0; off >>= 1) {
        if ((int)threadIdx.x < off) red[threadIdx.x] += red[threadIdx.x + off];
        __syncthreads();
    }
    if (threadIdx.x == 0) g_partial[blockIdx.x] = red[0];
}

// 1 block, 1024 threads: scan partials -> chunk, then scan chunk -> exact key.
__global__ void select2_kernel() {
    __shared__ unsigned s[1024];
    __shared__ unsigned s_chunk, s_rank;
    int t = threadIdx.x;
    unsigned R = g_r1;

    unsigned local = g_partial[t];
    s[t] = local;
    __syncthreads();
    for (int off = 1; off < 1024; off <<= 1) {
        unsigned v = (t >= off) ? s[t - off] : 0u;
        __syncthreads();
        s[t] += v;
        __syncthreads();
    }
    unsigned incl   = s[t];
    unsigned before = incl - local;
    if (R > before && R <= incl) { s_chunk = (unsigned)t; s_rank = R - before; }
    __syncthreads();

    unsigned chunk = s_chunk;
    unsigned r2    = s_rank;

    unsigned local2 = g_hist2[chunk * 1024u + t];
    __syncthreads();
    s[t] = local2;
    __syncthreads();
    for (int off = 1; off < 1024; off <<= 1) {
        unsigned v = (t >= off) ? s[t - off] : 0u;
        __syncthreads();
        s[t] += v;
        __syncthreads();
    }
    unsigned incl2   = s[t];
    unsigned before2 = incl2 - local2;
    if (r2 > before2 && r2 <= incl2) {
        g_thr_key = (g_b1 << 20) | (chunk * 1024u + (unsigned)t);
    }
}

// ---------------------------------------------------------------------------
// Rewrite kept candidates (key >= thr); dropped candidates already hold 0.
__global__ void finalize_kernel(const float* __restrict__ xs,
                                float* __restrict__ out) {
    unsigned nc  = g_ncand;
    unsigned thr = g_thr_key;
    unsigned stride = gridDim.x * blockDim.x;
    for (unsigned i = blockIdx.x * blockDim.x + threadIdx.x; i < nc; i += stride) {
        uint2 r = g_cand[i];
        if (r.x >= thr) out[r.y] = xs[r.y];
    }
}

// ---------------------------------------------------------------------------
extern "C" void kernel_launch(void* const* d_in, const int* in_sizes, int n_in,
                              void* d_out, int out_size) {
    const float* xs = (const float*)d_in[0];
    const float* ms = (const float*)d_in[1];
    const float* sp = (const float*)d_in[2];
    // d_in[3] = mask (unused by the reference computation)
    const int* t_ptr = (n_in >= 5) ? (const int*)d_in[4] : nullptr;

    unsigned n = (unsigned)in_sizes[0];
    float* out = (float*)d_out;

    zero_kernel<<<512, 256>>>();
    hist1_kernel<<<NBLOCKS, NTHREADS>>>(xs, ms, t_ptr, n);
    select1_kernel<<<1, 1024>>>(sp, n);
    apply_compact_kernel<<<NBLOCKS, NTHREADS>>>(xs, ms, t_ptr, out, n);
    partial2_kernel<<<1024, 256>>>();
    select2_kernel<<<1, 1024>>>();
    finalize_kernel<<<296, 256>>>(xs, out);
}

// round 3
// speedup vs baseline: 3.0967x; 3.0967x over previous
#include <cuda_runtime.h>
#include <stdint.h>

// ---------------------------------------------------------------------------
// MagnitudePruning via 2-level radix select on s = t*magnitude + |x|
// (monotone surrogate: division by uniform (t+1) preserves rank).
//
// Pass 1: 12-bit top histogram (shared, warp-aggregated)       360 MB read
// select1: bin b1 + remaining rank r1
// Pass 2 (fused): write out for all non-b1 elements; compact   540 MB r/w
//         b1-candidates via SHARED staging (one global counter
//         atomic per 4096-elem tile), build low-20 hist
// partial2/select2: exact threshold key among candidates
// finalize: rewrite kept candidates only                        small
// ---------------------------------------------------------------------------

#define HIST1_SIZE 4096u          // top 12 bits
#define HIST2_SIZE (1u << 20)     // low 20 bits
#define NBLOCKS 1184              // 8 * 148 SMs
#define NTHREADS 256
#define N_MAX 45088768u

#define TILE_F4   1024u           // float4s per tile (= 4096 elements)
#define TILE_ELEM 4096u

__device__ unsigned int g_hist1[HIST1_SIZE];
__device__ unsigned int g_hist2[HIST2_SIZE];
__device__ unsigned int g_partial[1024];
__device__ unsigned int g_b1;
__device__ unsigned int g_r1;       // 1-based remaining rank within bin b1
__device__ unsigned int g_thr_key;
__device__ unsigned int g_ncand;
__device__ uint2        g_cand[N_MAX];   // {key, idx} for elements in bin b1

__device__ __forceinline__ unsigned int key_of(float x, float m, float tf) {
    // s = t*m + |x|, explicit non-fused rounding so all passes agree bit-exactly
    float s = __fadd_rn(__fmul_rn(tf, m), fabsf(x));
    return __float_as_uint(s);   // s >= 0 -> bits are order-preserving
}

__device__ __forceinline__ float read_tf(const int* t_ptr) {
    return t_ptr ? (float)(*t_ptr) : 1.0f;
}

// ---------------------------------------------------------------------------
__global__ void zero_kernel() {
    unsigned total = HIST2_SIZE + HIST1_SIZE;
    unsigned stride = gridDim.x * blockDim.x;
    for (unsigned i = blockIdx.x * blockDim.x + threadIdx.x; i < total; i += stride) {
        if (i < HIST2_SIZE) g_hist2[i] = 0u;
        else                g_hist1[i - HIST2_SIZE] = 0u;
    }
    if (blockIdx.x == 0 && threadIdx.x == 0) g_ncand = 0u;
}

// ---------------------------------------------------------------------------
__device__ __forceinline__ void agg_shared_add(unsigned* hist, unsigned bin) {
    unsigned act   = __activemask();
    unsigned peers = __match_any_sync(act, bin);
    int      leader = __ffs(peers) - 1;
    if ((int)(threadIdx.x & 31) == leader)
        atomicAdd(&hist[bin], (unsigned)__popc(peers));
}

__global__ void hist1_kernel(const float* __restrict__ xs,
                             const float* __restrict__ ms,
                             const int* __restrict__ t_ptr,
                             unsigned n) {
    __shared__ unsigned sh[HIST1_SIZE];
    for (unsigned i = threadIdx.x; i < HIST1_SIZE; i += blockDim.x) sh[i] = 0u;
    __syncthreads();

    float tf = read_tf(t_ptr);
    unsigned n4 = n >> 2;
    const float4* x4 = (const float4*)xs;
    const float4* m4 = (const float4*)ms;
    unsigned stride = gridDim.x * blockDim.x;
    for (unsigned i = blockIdx.x * blockDim.x + threadIdx.x; i < n4; i += stride) {
        float4 xv = x4[i];
        float4 mv = m4[i];
        agg_shared_add(sh, key_of(xv.x, mv.x, tf) >> 20);
        agg_shared_add(sh, key_of(xv.y, mv.y, tf) >> 20);
        agg_shared_add(sh, key_of(xv.z, mv.z, tf) >> 20);
        agg_shared_add(sh, key_of(xv.w, mv.w, tf) >> 20);
    }
    // scalar tail
    if (blockIdx.x == 0 && threadIdx.x == 0) {
        for (unsigned i = n4 << 2; i < n; i++)
            atomicAdd(&g_hist1[key_of(xs[i], ms[i], tf) >> 20], 1u);
    }
    __syncthreads();
    for (unsigned i = threadIdx.x; i < HIST1_SIZE; i += blockDim.x) {
        unsigned c = sh[i];
        if (c) atomicAdd(&g_hist1[i], c);
    }
}

// ---------------------------------------------------------------------------
// 1 block, 1024 threads. Computes rank R from sparsity and scans the 4096-bin
// histogram to find bin b1 and the remaining rank r1 (1-based).
__global__ void select1_kernel(const float* __restrict__ sparsity, unsigned n) {
    __shared__ unsigned s[1024];
    int t = threadIdx.x;

    unsigned c0 = g_hist1[t * 4 + 0];
    unsigned c1 = g_hist1[t * 4 + 1];
    unsigned c2 = g_hist1[t * 4 + 2];
    unsigned c3 = g_hist1[t * 4 + 3];
    unsigned local = c0 + c1 + c2 + c3;

    s[t] = local;
    __syncthreads();
    for (int off = 1; off < 1024; off <<= 1) {
        unsigned v = (t >= off) ? s[t - off] : 0u;
        __syncthreads();
        s[t] += v;
        __syncthreads();
    }

    // R = idx+1, idx = clip((int)floor(sparsity*n - 1), 0, n-1)  (fp32 math, like jnp)
    float sp   = sparsity[0];
    float fidx = floorf(__fsub_rn(__fmul_rn(sp, (float)n), 1.0f));
    long long idx = (long long)fidx;
    if (idx < 0) idx = 0;
    if (idx > (long long)(n - 1)) idx = (long long)(n - 1);
    unsigned R = (unsigned)idx + 1u;

    unsigned incl   = s[t];
    unsigned before = incl - local;
    if (R > before && R <= incl) {
        unsigned run = before;
        unsigned c[4] = {c0, c1, c2, c3};
        #pragma unroll
        for (int j = 0; j < 4; j++) {
            if (R <= run + c[j]) {
                g_b1 = (unsigned)(t * 4 + j);
                g_r1 = R - run;
                break;
            }
            run += c[j];
        }
    }
}

// ---------------------------------------------------------------------------
// Fused pass with shared-memory candidate staging.
// Each tile = 1024 float4s (4096 elems). Per block-tile:
//   - decide & write out for non-candidates (float4 store)
//   - candidates -> shared buffer (warp-ballot + one shared atomic per group)
//   - one global atomicAdd(&g_ncand, cnt) per tile, coalesced flush + hist2
__device__ __forceinline__ void stage_cand(uint2* s_buf, unsigned* s_cnt,
                                           bool cand, unsigned key, unsigned idx) {
    unsigned ball = __ballot_sync(0xFFFFFFFFu, cand);
    if (ball) {
        int leader = __ffs(ball) - 1;
        unsigned base = 0;
        if ((int)(threadIdx.x & 31) == leader)
            base = atomicAdd(s_cnt, (unsigned)__popc(ball));
        base = __shfl_sync(0xFFFFFFFFu, base, leader);
        if (cand) {
            unsigned pos = base + (unsigned)__popc(ball & ((1u << (threadIdx.x & 31)) - 1u));
            s_buf[pos] = make_uint2(key, idx);
        }
    }
}

__global__ void apply_compact_kernel(const float* __restrict__ xs,
                                     const float* __restrict__ ms,
                                     const int* __restrict__ t_ptr,
                                     float* __restrict__ out,
                                     unsigned n) {
    __shared__ uint2    s_buf[TILE_ELEM];
    __shared__ unsigned s_cnt;
    __shared__ unsigned s_base;

    float tf = read_tf(t_ptr);
    unsigned b1 = g_b1;
    unsigned n4 = n >> 2;
    const float4* x4 = (const float4*)xs;
    const float4* m4 = (const float4*)ms;
    float4* o4 = (float4*)out;

    unsigned ntiles = (n4 + TILE_F4 - 1u) / TILE_F4;

    for (unsigned tile = blockIdx.x; tile < ntiles; tile += gridDim.x) {
        if (threadIdx.x == 0) s_cnt = 0u;
        __syncthreads();

        unsigned tbase = tile * TILE_F4;
        #pragma unroll
        for (int k = 0; k < 4; k++) {
            unsigned i = tbase + (unsigned)k * 256u + threadIdx.x;
            if (i < n4) {
                float4 xv = x4[i];
                float4 mv = m4[i];
                unsigned e = i * 4u;
                unsigned k0 = key_of(xv.x, mv.x, tf);
                unsigned k1 = key_of(xv.y, mv.y, tf);
                unsigned k2 = key_of(xv.z, mv.z, tf);
                unsigned k3 = key_of(xv.w, mv.w, tf);
                float4 ov;
                ov.x = ((k0 >> 20) > b1) ? xv.x : 0.0f;
                ov.y = ((k1 >> 20) > b1) ? xv.y : 0.0f;
                ov.z = ((k2 >> 20) > b1) ? xv.z : 0.0f;
                ov.w = ((k3 >> 20) > b1) ? xv.w : 0.0f;
                o4[i] = ov;
                stage_cand(s_buf, &s_cnt, (k0 >> 20) == b1, k0, e + 0u);
                stage_cand(s_buf, &s_cnt, (k1 >> 20) == b1, k1, e + 1u);
                stage_cand(s_buf, &s_cnt, (k2 >> 20) == b1, k2, e + 2u);
                stage_cand(s_buf, &s_cnt, (k3 >> 20) == b1, k3, e + 3u);
            } else {
                // keep warp convergent for ballots with no candidates
                stage_cand(s_buf, &s_cnt, false, 0u, 0u);
                stage_cand(s_buf, &s_cnt, false, 0u, 0u);
                stage_cand(s_buf, &s_cnt, false, 0u, 0u);
                stage_cand(s_buf, &s_cnt, false, 0u, 0u);
            }
        }
        __syncthreads();

        unsigned cnt = s_cnt;
        if (cnt) {
            if (threadIdx.x == 0) s_base = atomicAdd(&g_ncand, cnt);
            __syncthreads();
            unsigned base = s_base;
            for (unsigned j = threadIdx.x; j < cnt; j += blockDim.x) {
                uint2 r = s_buf[j];
                g_cand[base + j] = r;
                atomicAdd(&g_hist2[r.x & 0xFFFFFu], 1u);
            }
        }
        __syncthreads();
    }

    // scalar tail (n % 4) — n4*4..n
    if (blockIdx.x == 0 && threadIdx.x == 0) {
        for (unsigned i = n4 << 2; i < n; i++) {
            unsigned k = key_of(xs[i], ms[i], tf);
            unsigned top = k >> 20;
            out[i] = (top > b1) ? xs[i] : 0.0f;
            if (top == b1) {
                unsigned pos = atomicAdd(&g_ncand, 1u);
                g_cand[pos] = make_uint2(k, i);
                atomicAdd(&g_hist2[k & 0xFFFFFu], 1u);
            }
        }
    }
}

// ---------------------------------------------------------------------------
// 1024 blocks x 256 threads: chunk sums of the 1M-bin candidate histogram.
__global__ void partial2_kernel() {
    __shared__ unsigned red[256];
    unsigned base = blockIdx.x * 1024u;
    unsigned sum = 0;
    for (unsigned i = threadIdx.x; i < 1024u; i += 256u) sum += g_hist2[base + i];
    red[threadIdx.x] = sum;
    __syncthreads();
    for (int off = 128; off > 0; off >>= 1) {
        if ((int)threadIdx.x < off) red[threadIdx.x] += red[threadIdx.x + off];
        __syncthreads();
    }
    if (threadIdx.x == 0) g_partial[blockIdx.x] = red[0];
}

// 1 block, 1024 threads: scan partials -> chunk, then scan chunk -> exact key.
__global__ void select2_kernel() {
    __shared__ unsigned s[1024];
    __shared__ unsigned s_chunk, s_rank;
    int t = threadIdx.x;
    unsigned R = g_r1;

    unsigned local = g_partial[t];
    s[t] = local;
    __syncthreads();
    for (int off = 1; off < 1024; off <<= 1) {
        unsigned v = (t >= off) ? s[t - off] : 0u;
        __syncthreads();
        s[t] += v;
        __syncthreads();
    }
    unsigned incl   = s[t];
    unsigned before = incl - local;
    if (R > before && R <= incl) { s_chunk = (unsigned)t; s_rank = R - before; }
    __syncthreads();

    unsigned chunk = s_chunk;
    unsigned r2    = s_rank;

    unsigned local2 = g_hist2[chunk * 1024u + t];
    __syncthreads();
    s[t] = local2;
    __syncthreads();
    for (int off = 1; off < 1024; off <<= 1) {
        unsigned v = (t >= off) ? s[t - off] : 0u;
        __syncthreads();
        s[t] += v;
        __syncthreads();
    }
    unsigned incl2   = s[t];
    unsigned before2 = incl2 - local2;
    if (r2 > before2 && r2 <= incl2) {
        g_thr_key = (g_b1 << 20) | (chunk * 1024u + (unsigned)t);
    }
}

// ---------------------------------------------------------------------------
// Rewrite kept candidates (key >= thr); dropped candidates already hold 0.
__global__ void finalize_kernel(const float* __restrict__ xs,
                                float* __restrict__ out) {
    unsigned nc  = g_ncand;
    unsigned thr = g_thr_key;
    unsigned stride = gridDim.x * blockDim.x;
    for (unsigned i = blockIdx.x * blockDim.x + threadIdx.x; i < nc; i += stride) {
        uint2 r = g_cand[i];
        if (r.x >= thr) out[r.y] = xs[r.y];
    }
}

// ---------------------------------------------------------------------------
extern "C" void kernel_launch(void* const* d_in, const int* in_sizes, int n_in,
                              void* d_out, int out_size) {
    const float* xs = (const float*)d_in[0];
    const float* ms = (const float*)d_in[1];
    const float* sp = (const float*)d_in[2];
    // d_in[3] = mask (unused by the reference computation)
    const int* t_ptr = (n_in >= 5) ? (const int*)d_in[4] : nullptr;

    unsigned n = (unsigned)in_sizes[0];
    float* out = (float*)d_out;

    zero_kernel<<<512, 256>>>();
    hist1_kernel<<<NBLOCKS, NTHREADS>>>(xs, ms, t_ptr, n);
    select1_kernel<<<1, 1024>>>(sp, n);
    apply_compact_kernel<<<NBLOCKS, NTHREADS>>>(xs, ms, t_ptr, out, n);
    partial2_kernel<<<1024, 256>>>();
    select2_kernel<<<1, 1024>>>();
    finalize_kernel<<<1184, 256>>>(xs, out);
}

// round 4
// speedup vs baseline: 5.1800x; 1.6727x over previous
#include <cuda_runtime.h>
#include <stdint.h>

// ---------------------------------------------------------------------------
// MagnitudePruning via sampled-window radix select on s = t*magnitude + |x|
// (monotone surrogate: division by uniform (t+1) preserves rank).
//
// zero     : clear counters/histograms
// sample   : ~1M strided samples -> 4096-bin hist -> window [b_lo,b_hi]
// passA    : ONE full fused pass: exact below-count, write out for
//            out-of-window, compact in-window candidates to per-block
//            regions, shared window histogram
// candfilt : per-block select1 (b1, r1 exact) + hist2 of b1 candidates
// partial2 : chunk sums of 1M-bin hist2
// select2  : exact threshold key
// finalize : rewrite kept candidates (or single-block exact fallback)
// ---------------------------------------------------------------------------

#define SAMP_BINS  4096u          // top 12 bits
#define WBINS      1024u          // window width cap (bins)
#define HIST2_SIZE (1u << 20)     // low 20 bits
#define NBLOCKS    1184u
#define NTHREADS   256u
#define TILE_F4    512u           // float4s per tile (2048 elements)
#define TILE_ELEM  2048u
#define PER_BLOCK  40960u         // candidate region capacity per block

__device__ unsigned g_samp_hist[SAMP_BINS];
__device__ unsigned g_whist[WBINS];
__device__ unsigned g_hist2[HIST2_SIZE];
__device__ unsigned g_partial[1024];
__device__ unsigned g_below;
__device__ unsigned g_done;
__device__ unsigned g_ovf;
__device__ unsigned g_fb;
__device__ unsigned g_blo, g_bhi;
__device__ unsigned g_b1, g_r1, g_thr_key;
__device__ unsigned g_blk_cnt[NBLOCKS];
__device__ uint2    g_cand[NBLOCKS * PER_BLOCK];

__device__ __forceinline__ unsigned key_of(float x, float m, float tf) {
    float s = __fadd_rn(__fmul_rn(tf, m), fabsf(x));
    return __float_as_uint(s);
}
__device__ __forceinline__ float read_tf(const int* t_ptr) {
    return t_ptr ? (float)(*t_ptr) : 1.0f;
}
__device__ __forceinline__ unsigned rank_R(const float* sp, unsigned n) {
    float fidx = floorf(__fsub_rn(__fmul_rn(sp[0], (float)n), 1.0f));
    long long idx = (long long)fidx;
    if (idx < 0) idx = 0;
    if (idx > (long long)(n - 1)) idx = (long long)(n - 1);
    return (unsigned)idx + 1u;
}
__device__ __forceinline__ void agg_shared_add(unsigned* hist, unsigned bin) {
    unsigned act    = __activemask();
    unsigned peers  = __match_any_sync(act, bin);
    int      leader = __ffs(peers) - 1;
    if ((int)(threadIdx.x & 31) == leader)
        atomicAdd(&hist[bin], (unsigned)__popc(peers));
}

// ---------------------------------------------------------------------------
__global__ void zero_kernel() {
    unsigned stride = gridDim.x * blockDim.x;
    unsigned tid = blockIdx.x * blockDim.x + threadIdx.x;
    for (unsigned i = tid; i < HIST2_SIZE; i += stride) g_hist2[i] = 0u;
    for (unsigned i = tid; i < SAMP_BINS;  i += stride) g_samp_hist[i] = 0u;
    for (unsigned i = tid; i < WBINS;      i += stride) g_whist[i] = 0u;
    if (tid == 0) { g_below = 0u; g_done = 0u; g_ovf = 0u; g_fb = 0u; }
}

// ---------------------------------------------------------------------------
// Sample ~1M elements (256K float4s evenly strided), 4096-bin hist; the last
// block to finish computes the window [b_lo, b_hi] (rank margin +-1%).
__global__ void sample_kernel(const float* __restrict__ xs,
                              const float* __restrict__ ms,
                              const int* __restrict__ t_ptr,
                              const float* __restrict__ sparsity,
                              unsigned n) {
    __shared__ unsigned sh[SAMP_BINS];
    for (unsigned i = threadIdx.x; i < SAMP_BINS; i += blockDim.x) sh[i] = 0u;
    __syncthreads();

    float tf = read_tf(t_ptr);
    unsigned n4 = n >> 2;
    unsigned stride4 = n4 / 262144u; if (stride4 == 0u) stride4 = 1u;
    unsigned nsamp4  = n4 / stride4;
    const float4* x4 = (const float4*)xs;
    const float4* m4 = (const float4*)ms;

    unsigned gstride = gridDim.x * blockDim.x;
    for (unsigned i = blockIdx.x * blockDim.x + threadIdx.x; i < nsamp4; i += gstride) {
        unsigned idx = i * stride4;
        float4 xv = x4[idx];
        float4 mv = m4[idx];
        agg_shared_add(sh, key_of(xv.x, mv.x, tf) >> 20);
        agg_shared_add(sh, key_of(xv.y, mv.y, tf) >> 20);
        agg_shared_add(sh, key_of(xv.z, mv.z, tf) >> 20);
        agg_shared_add(sh, key_of(xv.w, mv.w, tf) >> 20);
    }
    __syncthreads();
    for (unsigned i = threadIdx.x; i < SAMP_BINS; i += blockDim.x) {
        unsigned c = sh[i];
        if (c) atomicAdd(&g_samp_hist[i], c);
    }
    __threadfence();

    __shared__ unsigned slast;
    if (threadIdx.x == 0)
        slast = (atomicAdd(&g_done, 1u) == gridDim.x - 1u) ? 1u : 0u;
    __syncthreads();
    if (!slast) return;

    // ---- last block: compute window ----
    __shared__ unsigned sscan[256];
    __shared__ unsigned svlo, svhi;
    int t = threadIdx.x;               // 256 threads, 16 bins each
    unsigned loc[16];
    unsigned lsum = 0u;
    #pragma unroll
    for (int j = 0; j < 16; j++) { loc[j] = g_samp_hist[t * 16 + j]; lsum += loc[j]; }
    sscan[t] = lsum;
    __syncthreads();
    for (int off = 1; off < 256; off <<= 1) {
        unsigned v = (t >= off) ? sscan[t - off] : 0u;
        __syncthreads();
        sscan[t] += v;
        __syncthreads();
    }
    unsigned incl  = sscan[t];
    unsigned total = sscan[255];
    unsigned before = incl - lsum;

    unsigned R = rank_R(sparsity, n);
    float f = (float)R / (float)n;
    float tlo = (f - 0.01f) * (float)total;
    float thi = (f + 0.01f) * (float)total + 1.0f;
    unsigned slo = (tlo < 1.0f) ? 1u : (unsigned)tlo;
    if (slo > total) slo = total;
    unsigned shi = (thi < 1.0f) ? 1u : (unsigned)thi;
    if (shi > total) shi = total;
    if (shi < slo) shi = slo;

    // locate bins containing sample-ranks slo and shi
    if (slo > before && slo <= incl) {
        unsigned run = before;
        #pragma unroll
        for (int j = 0; j < 16; j++) {
            if (slo <= run + loc[j]) { svlo = (unsigned)(t * 16 + j); break; }
            run += loc[j];
        }
    }
    if (shi > before && shi <= incl) {
        unsigned run = before;
        #pragma unroll
        for (int j = 0; j < 16; j++) {
            if (shi <= run + loc[j]) { svhi = (unsigned)(t * 16 + j); break; }
            run += loc[j];
        }
    }
    __syncthreads();
    if (t == 0) {
        unsigned blo = svlo, bhi = svhi;
        if (bhi < blo) bhi = blo;
        if (bhi - blo + 1u > WBINS) bhi = blo + WBINS - 1u;
        g_blo = blo; g_bhi = bhi;
    }
}

// ---------------------------------------------------------------------------
// The single fused full pass.
__global__ void passA_kernel(const float* __restrict__ xs,
                             const float* __restrict__ ms,
                             const int* __restrict__ t_ptr,
                             float* __restrict__ out,
                             unsigned n) {
    __shared__ uint2    s_buf[TILE_ELEM];
    __shared__ unsigned s_whist[WBINS];
    __shared__ unsigned s_cnt;
    __shared__ unsigned s_red[NTHREADS];

    for (unsigned i = threadIdx.x; i < WBINS; i += blockDim.x) s_whist[i] = 0u;

    float tf = read_tf(t_ptr);
    unsigned b_lo = g_blo, b_hi = g_bhi;
    unsigned n4 = n >> 2;
    const float4* x4 = (const float4*)xs;
    const float4* m4 = (const float4*)ms;
    float4* o4 = (float4*)out;

    unsigned region = blockIdx.x * PER_BLOCK;
    unsigned nreg = 0u;
    unsigned below = 0u;
    unsigned ntiles = (n4 + TILE_F4 - 1u) / TILE_F4;

    for (unsigned tile = blockIdx.x; tile < ntiles; tile += gridDim.x) {
        if (threadIdx.x == 0) s_cnt = 0u;
        __syncthreads();

        unsigned tbase = tile * TILE_F4;
        #pragma unroll
        for (int k = 0; k < 2; k++) {
            unsigned i = tbase + (unsigned)k * NTHREADS + threadIdx.x;
            if (i < n4) {
                float4 xv = x4[i];
                float4 mv = m4[i];
                unsigned e = i * 4u;
                unsigned kk[4];
                kk[0] = key_of(xv.x, mv.x, tf);
                kk[1] = key_of(xv.y, mv.y, tf);
                kk[2] = key_of(xv.z, mv.z, tf);
                kk[3] = key_of(xv.w, mv.w, tf);
                float vv[4] = {xv.x, xv.y, xv.z, xv.w};
                float ov[4];
                #pragma unroll
                for (int j = 0; j < 4; j++) {
                    unsigned top = kk[j] >> 20;
                    below += (top < b_lo) ? 1u : 0u;
                    ov[j] = (top > b_hi) ? vv[j] : 0.0f;
                    if (top >= b_lo && top <= b_hi) {
                        unsigned pos = atomicAdd(&s_cnt, 1u);
                        s_buf[pos] = make_uint2(kk[j], e + (unsigned)j);
                        agg_shared_add(s_whist, top - b_lo);
                    }
                }
                o4[i] = make_float4(ov[0], ov[1], ov[2], ov[3]);
            }
        }
        __syncthreads();

        unsigned cnt = s_cnt;
        if (cnt) {
            if (nreg + cnt <= PER_BLOCK) {
                for (unsigned j = threadIdx.x; j < cnt; j += blockDim.x)
                    g_cand[region + nreg + j] = s_buf[j];
                nreg += cnt;
            } else {
                if (threadIdx.x == 0) atomicExch(&g_ovf, 1u);
            }
        }
        __syncthreads();
    }

    // scalar tail (n % 4) — rare; handled by block 0 / thread 0
    if (blockIdx.x == 0 && threadIdx.x == 0) {
        for (unsigned i = n4 << 2; i < n; i++) {
            unsigned k = key_of(xs[i], ms[i], tf);
            unsigned top = k >> 20;
            below += (top < b_lo) ? 1u : 0u;
            out[i] = (top > b_hi) ? xs[i] : 0.0f;
            if (top >= b_lo && top <= b_hi) {
                if (nreg < PER_BLOCK) {
                    g_cand[region + nreg] = make_uint2(k, i);
                    nreg++;
                    atomicAdd(&s_whist[top - b_lo], 1u);
                } else {
                    atomicExch(&g_ovf, 1u);
                }
            }
        }
    }
    __syncthreads();

    if (threadIdx.x == 0) g_blk_cnt[blockIdx.x] = nreg;

    // reduce below-count: one global atomic per block
    s_red[threadIdx.x] = below;
    __syncthreads();
    for (int off = NTHREADS / 2; off > 0; off >>= 1) {
        if ((int)threadIdx.x < off) s_red[threadIdx.x] += s_red[threadIdx.x + off];
        __syncthreads();
    }
    if (threadIdx.x == 0 && s_red[0]) atomicAdd(&g_below, s_red[0]);

    // flush window hist
    for (unsigned i = threadIdx.x; i < WBINS; i += blockDim.x) {
        unsigned c = s_whist[i];
        if (c) atomicAdd(&g_whist[i], c);
    }
}

// ---------------------------------------------------------------------------
// Every block redundantly computes (b1, r1) from g_whist/g_below, then
// histograms the low-20 bits of its own region's b1-candidates.
__global__ void candfilter_kernel(const float* __restrict__ sparsity, unsigned n) {
    __shared__ unsigned ss[NTHREADS];
    __shared__ unsigned sb1, sr1;
    int t = threadIdx.x;
    if (t == 0) { sb1 = 0xFFFFFFFFu; sr1 = 1u; }

    unsigned c[4];
    unsigned local = 0u;
    #pragma unroll
    for (int j = 0; j < 4; j++) { c[j] = g_whist[t * 4 + j]; local += c[j]; }
    ss[t] = local;
    __syncthreads();
    for (int off = 1; off < NTHREADS; off <<= 1) {
        unsigned v = (t >= off) ? ss[t - off] : 0u;
        __syncthreads();
        ss[t] += v;
        __syncthreads();
    }
    unsigned incl   = ss[t];
    unsigned total  = ss[NTHREADS - 1];
    unsigned before = incl - local;

    unsigned below = g_below;
    unsigned R = rank_R(sparsity, n);
    bool fb = (below >= R) || ((R - below) > total) || (g_ovf != 0u);
    unsigned Rp = R - below;

    if (!fb && Rp > before && Rp <= incl) {
        unsigned run = before;
        #pragma unroll
        for (int j = 0; j < 4; j++) {
            if (Rp <= run + c[j]) {
                sb1 = g_blo + (unsigned)(t * 4 + j);
                sr1 = Rp - run;
                break;
            }
            run += c[j];
        }
    }
    __syncthreads();

    if (blockIdx.x == 0 && t == 0) {
        g_fb = fb ? 1u : 0u;
        if (!fb) { g_b1 = sb1; g_r1 = sr1; }
    }
    if (fb) return;

    unsigned b1 = sb1;
    unsigned cnt    = g_blk_cnt[blockIdx.x];
    unsigned region = blockIdx.x * PER_BLOCK;
    for (unsigned j = (unsigned)t; j < cnt; j += blockDim.x) {
        uint2 r = g_cand[region + j];
        if ((r.x >> 20) == b1) atomicAdd(&g_hist2[r.x & 0xFFFFFu], 1u);
    }
}

// ---------------------------------------------------------------------------
__global__ void partial2_kernel() {
    __shared__ unsigned red[256];
    unsigned base = blockIdx.x * 1024u;
    unsigned sum = 0;
    for (unsigned i = threadIdx.x; i < 1024u; i += 256u) sum += g_hist2[base + i];
    red[threadIdx.x] = sum;
    __syncthreads();
    for (int off = 128; off > 0; off >>= 1) {
        if ((int)threadIdx.x < off) red[threadIdx.x] += red[threadIdx.x + off];
        __syncthreads();
    }
    if (threadIdx.x == 0) g_partial[blockIdx.x] = red[0];
}

__global__ void select2_kernel() {
    __shared__ unsigned s[1024];
    __shared__ unsigned s_chunk, s_rank;
    int t = threadIdx.x;
    if (t == 0) { s_chunk = 0u; s_rank = 1u; }
    unsigned R = g_r1;

    unsigned local = g_partial[t];
    s[t] = local;
    __syncthreads();
    for (int off = 1; off < 1024; off <<= 1) {
        unsigned v = (t >= off) ? s[t - off] : 0u;
        __syncthreads();
        s[t] += v;
        __syncthreads();
    }
    unsigned incl   = s[t];
    unsigned before = incl - local;
    if (R > before && R <= incl) { s_chunk = (unsigned)t; s_rank = R - before; }
    __syncthreads();

    unsigned chunk = s_chunk;
    unsigned r2    = s_rank;

    unsigned local2 = g_hist2[chunk * 1024u + t];
    __syncthreads();
    s[t] = local2;
    __syncthreads();
    for (int off = 1; off < 1024; off <<= 1) {
        unsigned v = (t >= off) ? s[t - off] : 0u;
        __syncthreads();
        s[t] += v;
        __syncthreads();
    }
    unsigned incl2   = s[t];
    unsigned before2 = incl2 - local2;
    if (r2 > before2 && r2 <= incl2) {
        g_thr_key = (g_b1 << 20) | (chunk * 1024u + (unsigned)t);
    }
}

// ---------------------------------------------------------------------------
// Normal: rewrite kept candidates. Fallback (never in practice): block 0
// redoes the whole selection exactly, single-block, 3-level radix.
__global__ void finalize_kernel(const float* __restrict__ xs,
                                const float* __restrict__ ms,
                                const int* __restrict__ t_ptr,
                                const float* __restrict__ sparsity,
                                float* __restrict__ out,
                                unsigned n) {
    if (g_fb) {
        if (blockIdx.x != 0) return;
        __shared__ unsigned sh[4096];
        __shared__ unsigned sv[4];   // b1, b2, b3/thr scratch
        float tf = read_tf(t_ptr);
        unsigned R = rank_R(sparsity, n);
        int t = threadIdx.x;

        // level 1: top 12 bits
        for (unsigned i = t; i < 4096u; i += blockDim.x) sh[i] = 0u;
        __syncthreads();
        for (unsigned i = t; i < n; i += blockDim.x)
            atomicAdd(&sh[key_of(xs[i], ms[i], tf) >> 20], 1u);
        __syncthreads();
        if (t == 0) {
            unsigned run = 0u;
            for (unsigned b = 0; b < 4096u; b++) {
                if (R <= run + sh[b]) { sv[0] = b; sv[1] = R - run; break; }
                run += sh[b];
            }
        }
        __syncthreads();
        unsigned b1 = sv[0], r1 = sv[1];

        // level 2: bits [10,20)
        for (unsigned i = t; i < 1024u; i += blockDim.x) sh[i] = 0u;
        __syncthreads();
        for (unsigned i = t; i < n; i += blockDim.x) {
            unsigned k = key_of(xs[i], ms[i], tf);
            if ((k >> 20) == b1) atomicAdd(&sh[(k >> 10) & 1023u], 1u);
        }
        __syncthreads();
        if (t == 0) {
            unsigned run = 0u;
            for (unsigned b = 0; b < 1024u; b++) {
                if (r1 <= run + sh[b]) { sv[2] = b; sv[1] = r1 - run; break; }
                run += sh[b];
            }
        }
        __syncthreads();
        unsigned b2 = sv[2], r2 = sv[1];
        unsigned pre = (b1 << 10) | b2;

        // level 3: bits [0,10)
        for (unsigned i = t; i < 1024u; i += blockDim.x) sh[i] = 0u;
        __syncthreads();
        for (unsigned i = t; i < n; i += blockDim.x) {
            unsigned k = key_of(xs[i], ms[i], tf);
            if ((k >> 10) == pre) atomicAdd(&sh[k & 1023u], 1u);
        }
        __syncthreads();
        if (t == 0) {
            unsigned run = 0u;
            for (unsigned b = 0; b < 1024u; b++) {
                if (r2 <= run + sh[b]) { sv[3] = (pre << 10) | b; break; }
                run += sh[b];
            }
        }
        __syncthreads();
        unsigned thr = sv[3];

        for (unsigned i = t; i < n; i += blockDim.x) {
            unsigned k = key_of(xs[i], ms[i], tf);
            out[i] = (k >= thr) ? xs[i] : 0.0f;
        }
        return;
    }

    unsigned b1  = g_b1;
    unsigned thr = g_thr_key;
    unsigned cnt    = g_blk_cnt[blockIdx.x];
    unsigned region = blockIdx.x * PER_BLOCK;
    for (unsigned j = threadIdx.x; j < cnt; j += blockDim.x) {
        uint2 r = g_cand[region + j];
        unsigned top = r.x >> 20;
        if (top > b1 || (top == b1 && r.x >= thr)) out[r.y] = xs[r.y];
    }
}

// ---------------------------------------------------------------------------
extern "C" void kernel_launch(void* const* d_in, const int* in_sizes, int n_in,
                              void* d_out, int out_size) {
    const float* xs = (const float*)d_in[0];
    const float* ms = (const float*)d_in[1];
    const float* sp = (const float*)d_in[2];
    // d_in[3] = mask (unused by the reference computation)
    const int* t_ptr = (n_in >= 5) ? (const int*)d_in[4] : nullptr;

    unsigned n = (unsigned)in_sizes[0];
    float* out = (float*)d_out;

    zero_kernel<<<148, 256>>>();
    sample_kernel<<<264, 256>>>(xs, ms, t_ptr, sp, n);
    passA_kernel<<<NBLOCKS, NTHREADS>>>(xs, ms, t_ptr, out, n);
    candfilter_kernel<<<NBLOCKS, NTHREADS>>>(sp, n);
    partial2_kernel<<<1024, 256>>>();
    select2_kernel<<<1, 1024>>>();
    finalize_kernel<<<NBLOCKS, NTHREADS>>>(xs, ms, t_ptr, sp, out, n);
}